// round 2
// baseline (speedup 1.0000x reference)
#include <cuda_runtime.h>
#include <cuda_bf16.h>
#include <cstdint>

#define EPSF 1e-5f

constexpr int MROWS = 16384;
constexpr int KDIM  = 1024;
constexpr int NDIM  = 1024;

// GEMM tiling: CTA = 128(M) x 128(N), K-chunk = 128 int8 bytes, 8 chunks total.
constexpr int KT          = KDIM / 128;      // 8
constexpr int STAGES      = 3;
constexpr int A_TILE      = 128 * 128;       // 16KB
constexpr int B_TILE      = 128 * 128;       // 16KB
constexpr int STAGE_BYTES = A_TILE + B_TILE; // 32KB
constexpr int SMEM_TOTAL  = STAGES * STAGE_BYTES; // 96KB

// ---------------- device scratch (no allocations allowed) ----------------
__device__ char  g_qx[(size_t)MROWS * KDIM];  // 16MB int8, row-major [m][k]
__device__ char  g_qw[(size_t)NDIM  * KDIM];  // 1MB  int8, row-major [n][k]
__device__ float g_row_dq[MROWS];             // max|x_row| / 127
__device__ float g_partial[1024];
__device__ float g_w_factor;                  // clip(mean|w|, eps)

// ---------------- PTX helpers (baseline sm_80/sm_90 ISA only) -------------
__device__ __forceinline__ uint32_t smem_u32(const void* p) {
    uint32_t a;
    asm("{ .reg .u64 t; cvta.to.shared.u64 t, %1; cvt.u32.u64 %0, t; }" : "=r"(a) : "l"(p));
    return a;
}
__device__ __forceinline__ void cp16(uint32_t dst, const void* src) {
    asm volatile("cp.async.cg.shared.global [%0], [%1], 16;" :: "r"(dst), "l"(src));
}
__device__ __forceinline__ void cp_commit() {
    asm volatile("cp.async.commit_group;" ::: "memory");
}
__device__ __forceinline__ void cp_wait1() {
    asm volatile("cp.async.wait_group 1;" ::: "memory");
}
__device__ __forceinline__ void cp_wait0() {
    asm volatile("cp.async.wait_group 0;" ::: "memory");
}
__device__ __forceinline__ void ldm_x4(uint32_t* r, uint32_t addr) {
    asm volatile("ldmatrix.sync.aligned.m8n8.x4.shared.b16 {%0,%1,%2,%3}, [%4];"
                 : "=r"(r[0]), "=r"(r[1]), "=r"(r[2]), "=r"(r[3]) : "r"(addr));
}
__device__ __forceinline__ void mma_s8(int* d, const uint32_t* a, uint32_t b0, uint32_t b1) {
    asm volatile(
        "mma.sync.aligned.m16n8k32.row.col.s32.s8.s8.s32 "
        "{%0,%1,%2,%3}, {%4,%5,%6,%7}, {%8,%9}, {%0,%1,%2,%3};"
        : "+r"(d[0]), "+r"(d[1]), "+r"(d[2]), "+r"(d[3])
        : "r"(a[0]), "r"(a[1]), "r"(a[2]), "r"(a[3]), "r"(b0), "r"(b1));
}

// =========================================================================
// Weight |.| partial sums
// =========================================================================
__global__ void wabs_kernel(const float* __restrict__ w) {
    int b = blockIdx.x, t = threadIdx.x;
    float4 v = reinterpret_cast<const float4*>(w + (size_t)b * 1024)[t];
    float s = fabsf(v.x) + fabsf(v.y) + fabsf(v.z) + fabsf(v.w);
    #pragma unroll
    for (int o = 16; o; o >>= 1) s += __shfl_xor_sync(0xffffffffu, s, o);
    __shared__ float sm[8];
    if ((t & 31) == 0) sm[t >> 5] = s;
    __syncthreads();
    if (t == 0) {
        float tot = 0.f;
        #pragma unroll
        for (int i = 0; i < 8; i++) tot += sm[i];
        g_partial[b] = tot;
    }
}

__global__ void wscale_kernel() {
    int t = threadIdx.x;
    float4 v = reinterpret_cast<const float4*>(g_partial)[t];
    float s = v.x + v.y + v.z + v.w;
    #pragma unroll
    for (int o = 16; o; o >>= 1) s += __shfl_xor_sync(0xffffffffu, s, o);
    __shared__ float sm[8];
    if ((t & 31) == 0) sm[t >> 5] = s;
    __syncthreads();
    if (t == 0) {
        float tot = 0.f;
        #pragma unroll
        for (int i = 0; i < 8; i++) tot += sm[i];
        g_w_factor = fmaxf(tot / (float)(NDIM * KDIM), EPSF); // = 1 / w_scale
    }
}

// Ternary-quantize weight to int8 row-major [n][k]
__global__ void wquant_kernel(const float* __restrict__ w) {
    int n = blockIdx.x, t = threadIdx.x;
    float inv = 1.f / g_w_factor; // w_scale
    float4 v = reinterpret_cast<const float4*>(w + (size_t)n * 1024)[t];
    char4 c;
    c.x = (char)(int)fminf(fmaxf(rintf(v.x * inv), -1.f), 1.f);
    c.y = (char)(int)fminf(fmaxf(rintf(v.y * inv), -1.f), 1.f);
    c.z = (char)(int)fminf(fmaxf(rintf(v.z * inv), -1.f), 1.f);
    c.w = (char)(int)fminf(fmaxf(rintf(v.w * inv), -1.f), 1.f);
    *reinterpret_cast<char4*>(g_qw + (size_t)n * 1024 + 4 * t) = c;
}

// Per-row int8 quantize x to row-major [m][k]
__global__ void xquant_kernel(const float* __restrict__ x) {
    int r = blockIdx.x, t = threadIdx.x;
    float4 v = reinterpret_cast<const float4*>(x + (size_t)r * 1024)[t];
    float mx = fmaxf(fmaxf(fabsf(v.x), fabsf(v.y)), fmaxf(fabsf(v.z), fabsf(v.w)));
    #pragma unroll
    for (int o = 16; o; o >>= 1) mx = fmaxf(mx, __shfl_xor_sync(0xffffffffu, mx, o));
    __shared__ float sm[8];
    __shared__ float sbcast;
    if ((t & 31) == 0) sm[t >> 5] = mx;
    __syncthreads();
    if (t == 0) {
        float m2 = sm[0];
        #pragma unroll
        for (int i = 1; i < 8; i++) m2 = fmaxf(m2, sm[i]);
        m2 = fmaxf(m2, EPSF);
        sbcast = m2;
        g_row_dq[r] = m2 / 127.f;  // = 1 / act_scale
    }
    __syncthreads();
    float scale = 127.f / sbcast;
    char4 c;
    c.x = (char)(int)fminf(fmaxf(rintf(v.x * scale), -128.f), 127.f);
    c.y = (char)(int)fminf(fmaxf(rintf(v.y * scale), -128.f), 127.f);
    c.z = (char)(int)fminf(fmaxf(rintf(v.z * scale), -128.f), 127.f);
    c.w = (char)(int)fminf(fmaxf(rintf(v.w * scale), -128.f), 127.f);
    *reinterpret_cast<char4*>(g_qx + (size_t)r * 1024 + 4 * t) = c;
}

// =========================================================================
// IMMA GEMM: CTA 128x128, 8 warps (2M x 4N), warp tile 64x32,
// mma.m16n8k32.s8, cp.async 3-stage pipeline, XOR-swizzled smem.
// =========================================================================
__global__ void __launch_bounds__(256, 1)
gemm_kernel(const float* __restrict__ bias, float* __restrict__ out) {
    extern __shared__ __align__(128) char smem[];
    const uint32_t sb = smem_u32(smem);
    const int tid = threadIdx.x;
    const int wid = tid >> 5, lid = tid & 31;
    const int nt = blockIdx.x;   // 0..7
    const int mt = blockIdx.y;   // 0..127
    const int mh = wid >> 2;     // warp M half (0/1)
    const int nq = wid & 3;      // warp N quarter (0..3)

    const char* Aptr = g_qx + (size_t)mt * 128 * KDIM;
    const char* Bptr = g_qw + (size_t)nt * 128 * KDIM;

    // --- async copy of one K-chunk (128 bytes of K) into stage s ---
    auto issue = [&](int kt) {
        int s = kt % STAGES;
        uint32_t base = sb + s * STAGE_BYTES;
        const char* gA = Aptr + kt * 128;
        const char* gB = Bptr + kt * 128;
        #pragma unroll
        for (int r = 0; r < 4; r++) {
            int idx = tid + 256 * r;          // 0..1023
            int row = idx >> 3, c = idx & 7;  // row 0..127, 16B chunk 0..7
            uint32_t sw = (uint32_t)(row * 128 + ((c ^ (row & 7)) << 4));
            cp16(base + sw,          gA + (size_t)row * KDIM + c * 16);
            cp16(base + A_TILE + sw, gB + (size_t)row * KDIM + c * 16);
        }
        cp_commit();
    };

    int acc[4][4][4];
    #pragma unroll
    for (int i = 0; i < 4; i++)
        #pragma unroll
        for (int j = 0; j < 4; j++)
            #pragma unroll
            for (int r = 0; r < 4; r++) acc[i][j][r] = 0;

    // prefetch first STAGES-1 chunks
    issue(0);
    issue(1);

    const int tile  = lid >> 3;          // 0..3 within ldmatrix x4
    const int trow  = lid & 7;
    const int arow_b = 64 * mh + ((tile & 1) << 3) + trow;
    const int nrow_b = 32 * nq + ((tile & 1) << 3) + trow;
    const int kb_hi  = (tile >> 1) << 4; // 0 or 16 bytes

    for (int kt = 0; kt < KT; kt++) {
        if (kt >= KT - (STAGES - 1)) cp_wait0(); else cp_wait1();
        __syncthreads();
        if (kt + STAGES - 1 < KT) issue(kt + STAGES - 1);

        uint32_t Ab = sb + (kt % STAGES) * STAGE_BYTES;
        uint32_t Bb = Ab + A_TILE;

        #pragma unroll
        for (int ks = 0; ks < 4; ks++) {
            int kbyte = ks * 32 + kb_hi;
            uint32_t a[4][4];
            #pragma unroll
            for (int i = 0; i < 4; i++) {
                int ar = arow_b + 16 * i;
                ldm_x4(a[i], Ab + ar * 128 + ((((kbyte >> 4) ^ (ar & 7)) << 4)));
            }
            uint32_t b[2][4];
            #pragma unroll
            for (int j = 0; j < 2; j++) {
                int nr = nrow_b + 16 * j;
                ldm_x4(b[j], Bb + nr * 128 + ((((kbyte >> 4) ^ (nr & 7)) << 4)));
            }
            #pragma unroll
            for (int i = 0; i < 4; i++)
                #pragma unroll
                for (int jb = 0; jb < 4; jb++)
                    mma_s8(acc[i][jb], a[i], b[jb >> 1][jb & 1], b[jb >> 1][2 + (jb & 1)]);
        }
        __syncthreads();
    }

    // ---------------- epilogue: dequant + bias, float2 stores ----------------
    const float wf = g_w_factor;
    #pragma unroll
    for (int i = 0; i < 4; i++) {
        int r0 = mt * 128 + 64 * mh + 16 * i + (lid >> 2);
        float rf0 = g_row_dq[r0] * wf;
        float rf1 = g_row_dq[r0 + 8] * wf;
        float* o0 = out + (size_t)r0 * NDIM;
        float* o1 = out + (size_t)(r0 + 8) * NDIM;
        #pragma unroll
        for (int jb = 0; jb < 4; jb++) {
            int col = nt * 128 + 32 * nq + 8 * jb + ((lid & 3) << 1);
            float2 bz = *reinterpret_cast<const float2*>(&bias[col]);
            float2 v0, v1;
            v0.x = (float)acc[i][jb][0] * rf0 + bz.x;
            v0.y = (float)acc[i][jb][1] * rf0 + bz.y;
            v1.x = (float)acc[i][jb][2] * rf1 + bz.x;
            v1.y = (float)acc[i][jb][3] * rf1 + bz.y;
            *reinterpret_cast<float2*>(&o0[col]) = v0;
            *reinterpret_cast<float2*>(&o1[col]) = v1;
        }
    }
}

// =========================================================================
extern "C" void kernel_launch(void* const* d_in, const int* in_sizes, int n_in,
                              void* d_out, int out_size) {
    const float* x    = (const float*)d_in[0];
    const float* w    = (const float*)d_in[1];
    const float* bias = (const float*)d_in[2];
    float* out        = (float*)d_out;

    wabs_kernel<<<1024, 256>>>(w);
    wscale_kernel<<<1, 256>>>();
    wquant_kernel<<<1024, 256>>>(w);
    xquant_kernel<<<MROWS, 256>>>(x);

    cudaFuncSetAttribute(gemm_kernel, cudaFuncAttributeMaxDynamicSharedMemorySize, SMEM_TOTAL);
    gemm_kernel<<<dim3(NDIM / 128, MROWS / 128), 256, SMEM_TOTAL>>>(bias, out);
}